// round 1
// baseline (speedup 1.0000x reference)
#include <cuda_runtime.h>
#include <math.h>

// Problem constants (fixed shapes for HyperbolicMLR_33045478375870)
#define BDIM 4096   // batch rows
#define DDIM 1024   // feature dim
#define CDIM 4096   // classes
#define EPSV 1e-15f
#define MAXN 0.99999f  // (1 - 1e-5) / sqrt(c), c = 1

// Scratch (device globals — no allocations allowed)
__device__ float g_xp[(size_t)BDIM * DDIM];  // projected x
__device__ float g_x2[BDIM];                 // ||x_proj||^2
__device__ float g_p2[CDIM];                 // ||p_c||^2
__device__ float g_pa[CDIM];                 // <p_c, a_c>
__device__ float g_an[CDIM];                 // ||a_c||

// ---------------------------------------------------------------------------
// Kernel 1: project x onto the Poincare ball, store projected x and x2
// ---------------------------------------------------------------------------
__global__ __launch_bounds__(256) void proj_kernel(const float* __restrict__ x) {
    const int b = blockIdx.x;
    const float* xr = x + (size_t)b * DDIM;
    const int tid = threadIdx.x;

    float s = 0.f;
    #pragma unroll
    for (int i = tid; i < DDIM; i += 256) {
        float v = xr[i];
        s += v * v;
    }
    // warp reduce
    #pragma unroll
    for (int o = 16; o > 0; o >>= 1) s += __shfl_xor_sync(0xFFFFFFFFu, s, o);
    __shared__ float red[8];
    if ((tid & 31) == 0) red[tid >> 5] = s;
    __syncthreads();
    __shared__ float sh_scale, sh_x2;
    if (tid == 0) {
        float tot = 0.f;
        #pragma unroll
        for (int w = 0; w < 8; w++) tot += red[w];
        float xn = fmaxf(sqrtf(tot), EPSV);
        float scale = (xn > MAXN) ? (MAXN / xn) : 1.0f;
        sh_scale = scale;
        sh_x2 = tot * scale * scale;
        g_x2[b] = sh_x2;
    }
    __syncthreads();
    float sc = sh_scale;
    float* xo = g_xp + (size_t)b * DDIM;
    #pragma unroll
    for (int i = tid; i < DDIM; i += 256) xo[i] = xr[i] * sc;
}

// ---------------------------------------------------------------------------
// Kernel 2: per-class stats: p2, <p,a>, ||a||
// ---------------------------------------------------------------------------
__global__ __launch_bounds__(256) void stats_kernel(const float* __restrict__ a,
                                                    const float* __restrict__ p) {
    const int c = blockIdx.x;
    const float* ar = a + (size_t)c * DDIM;
    const float* pr = p + (size_t)c * DDIM;
    const int tid = threadIdx.x;

    float sp2 = 0.f, spa = 0.f, sa2 = 0.f;
    #pragma unroll
    for (int i = tid; i < DDIM; i += 256) {
        float av = ar[i], pv = pr[i];
        sp2 += pv * pv;
        spa += pv * av;
        sa2 += av * av;
    }
    #pragma unroll
    for (int o = 16; o > 0; o >>= 1) {
        sp2 += __shfl_xor_sync(0xFFFFFFFFu, sp2, o);
        spa += __shfl_xor_sync(0xFFFFFFFFu, spa, o);
        sa2 += __shfl_xor_sync(0xFFFFFFFFu, sa2, o);
    }
    __shared__ float r0[8], r1[8], r2[8];
    if ((tid & 31) == 0) { r0[tid >> 5] = sp2; r1[tid >> 5] = spa; r2[tid >> 5] = sa2; }
    __syncthreads();
    if (tid == 0) {
        float t0 = 0.f, t1 = 0.f, t2 = 0.f;
        #pragma unroll
        for (int w = 0; w < 8; w++) { t0 += r0[w]; t1 += r1[w]; t2 += r2[w]; }
        g_p2[c] = t0;
        g_pa[c] = t1;
        g_an[c] = sqrtf(t2);
    }
}

// ---------------------------------------------------------------------------
// Kernel 3: fused dual GEMM (px, xa) + hyperbolic MLR epilogue
// Tiles: BM=64 (batch), BN=64 (classes), BK=16, 4x4 register tile / thread
// ---------------------------------------------------------------------------
#define BM 64
#define BN 64
#define BK 16
#define TM 4
#define TN 4

__global__ __launch_bounds__(256) void mlr_kernel(const float* __restrict__ a,
                                                  const float* __restrict__ p,
                                                  float* __restrict__ out) {
    __shared__ float xs[BK][BM];
    __shared__ float ps[BK][BN];
    __shared__ float as_[BK][BN];

    const int tid = threadIdx.x;
    const int cb = blockIdx.x * BN;  // class tile origin
    const int rb = blockIdx.y * BM;  // batch tile origin

    float accP[TM][TN];
    float accA[TM][TN];
    #pragma unroll
    for (int i = 0; i < TM; i++)
        #pragma unroll
        for (int j = 0; j < TN; j++) { accP[i][j] = 0.f; accA[i][j] = 0.f; }

    // loader mapping: 256 threads load 64 rows x 16 cols (one float4 each)
    const int lrow = tid >> 2;          // 0..63
    const int lc4  = (tid & 3) << 2;    // 0,4,8,12

    const int tx = tid & 15;            // class sub-tile
    const int ty = tid >> 4;            // batch sub-tile

    const float* xbase = g_xp + (size_t)(rb + lrow) * DDIM + lc4;
    const float* pbase = p    + (size_t)(cb + lrow) * DDIM + lc4;
    const float* abase = a    + (size_t)(cb + lrow) * DDIM + lc4;

    for (int k0 = 0; k0 < DDIM; k0 += BK) {
        float4 xv = *(const float4*)(xbase + k0);
        float4 pv = *(const float4*)(pbase + k0);
        float4 av = *(const float4*)(abase + k0);
        xs[lc4 + 0][lrow] = xv.x; xs[lc4 + 1][lrow] = xv.y;
        xs[lc4 + 2][lrow] = xv.z; xs[lc4 + 3][lrow] = xv.w;
        ps[lc4 + 0][lrow] = pv.x; ps[lc4 + 1][lrow] = pv.y;
        ps[lc4 + 2][lrow] = pv.z; ps[lc4 + 3][lrow] = pv.w;
        as_[lc4 + 0][lrow] = av.x; as_[lc4 + 1][lrow] = av.y;
        as_[lc4 + 2][lrow] = av.z; as_[lc4 + 3][lrow] = av.w;
        __syncthreads();

        #pragma unroll
        for (int kk = 0; kk < BK; kk++) {
            float4 xr = *(const float4*)(&xs[kk][ty << 2]);
            float4 pr = *(const float4*)(&ps[kk][tx << 2]);
            float4 ar = *(const float4*)(&as_[kk][tx << 2]);
            const float xrv[TM] = {xr.x, xr.y, xr.z, xr.w};
            const float prv[TN] = {pr.x, pr.y, pr.z, pr.w};
            const float arv[TN] = {ar.x, ar.y, ar.z, ar.w};
            #pragma unroll
            for (int i = 0; i < TM; i++) {
                #pragma unroll
                for (int j = 0; j < TN; j++) {
                    accP[i][j] = fmaf(xrv[i], prv[j], accP[i][j]);
                    accA[i][j] = fmaf(xrv[i], arv[j], accA[i][j]);
                }
            }
        }
        __syncthreads();
    }

    // Epilogue (k = 1, sqrt_k = 1)
    #pragma unroll
    for (int i = 0; i < TM; i++) {
        const int b = rb + (ty << 2) + i;
        const float x2 = g_x2[b];
        float* orow = out + (size_t)b * CDIM + cb + (tx << 2);
        #pragma unroll
        for (int j = 0; j < TN; j++) {
            const int c = cb + (tx << 2) + j;
            const float px = accP[i][j];
            const float xa = accA[i][j];
            const float p2 = g_p2[c];
            const float pa = g_pa[c];
            const float an = g_an[c];

            const float A   = 1.0f - 2.0f * px + x2;
            const float Bc  = 1.0f - p2;
            const float den = fmaxf(1.0f - 2.0f * px + x2 * p2, EPSV);
            const float inv_den = 1.0f / den;
            const float dn2 = fmaxf((A * A * p2 + Bc * Bc * x2 - 2.0f * A * Bc * px)
                                        * (inv_den * inv_den), EPSV);
            const float scd = (-A * pa + Bc * xa) * inv_den;
            const float num = 2.0f * scd;
            const float dv  = (1.0f + dn2) * an;
            const float sgn = (dv > 0.f) ? 1.f : ((dv < 0.f) ? -1.f : 0.f);
            const float dcl = fmaxf(fabsf(dv), EPSV) * sgn;
            orow[j] = -asinhf(num / dcl);
        }
    }
}

// ---------------------------------------------------------------------------
extern "C" void kernel_launch(void* const* d_in, const int* in_sizes, int n_in,
                              void* d_out, int out_size) {
    const float* x = (const float*)d_in[0];
    const float* a = (const float*)d_in[1];
    const float* p = (const float*)d_in[2];
    float* out = (float*)d_out;

    proj_kernel<<<BDIM, 256>>>(x);
    stats_kernel<<<CDIM, 256>>>(a, p);
    dim3 grid(CDIM / BN, BDIM / BM);
    mlr_kernel<<<grid, 256>>>(a, p, out);
}

// round 3
// speedup vs baseline: 2.8906x; 2.8906x over previous
#include <cuda_runtime.h>
#include <cuda_bf16.h>
#include <math.h>
#include <cstdint>

// Fixed shapes for HyperbolicMLR_33045478375870
#define BDIM 4096
#define DDIM 1024
#define CDIM 4096
#define EPSV 1e-15f
#define MAXN 0.99999f   // (1 - 1e-5)/sqrt(c), c = 1

// ---------------------------------------------------------------------------
// Device scratch (no allocations allowed)
// ---------------------------------------------------------------------------
__device__ __nv_bfloat16 g_xhi[(size_t)BDIM * DDIM];
__device__ __nv_bfloat16 g_xlo[(size_t)BDIM * DDIM];
__device__ __nv_bfloat16 g_phi[(size_t)CDIM * DDIM];
__device__ __nv_bfloat16 g_plo[(size_t)CDIM * DDIM];
__device__ __nv_bfloat16 g_ahi[(size_t)CDIM * DDIM];
__device__ __nv_bfloat16 g_alo[(size_t)CDIM * DDIM];
__device__ float g_x2[BDIM];
__device__ float g_p2[CDIM];
__device__ float g_pa[CDIM];
__device__ float g_an[CDIM];

// ---------------------------------------------------------------------------
__device__ __forceinline__ uint32_t smem_u32(const void* p) {
    uint32_t a;
    asm("{ .reg .u64 t; cvta.to.shared.u64 t, %1; cvt.u32.u64 %0, t; }"
        : "=r"(a) : "l"(p));
    return a;
}

#define LDSM4(r, addr) \
    asm volatile("ldmatrix.sync.aligned.m8n8.x4.shared.b16 {%0,%1,%2,%3}, [%4];" \
                 : "=r"((r)[0]), "=r"((r)[1]), "=r"((r)[2]), "=r"((r)[3]) \
                 : "r"(addr))

#define MMA16816(c, a, b0, b1) \
    asm volatile("mma.sync.aligned.m16n8k16.row.col.f32.bf16.bf16.f32 " \
                 "{%0,%1,%2,%3},{%4,%5,%6,%7},{%8,%9},{%0,%1,%2,%3};" \
                 : "+f"((c)[0]), "+f"((c)[1]), "+f"((c)[2]), "+f"((c)[3]) \
                 : "r"((a)[0]), "r"((a)[1]), "r"((a)[2]), "r"((a)[3]), \
                   "r"(b0), "r"(b1))

#define CP_ASYNC16(dst, src) \
    asm volatile("cp.async.cg.shared.global [%0], [%1], 16;" \
                 :: "r"(dst), "l"(__cvta_generic_to_global(src)))

// ---------------------------------------------------------------------------
// Kernel 1: project x onto the ball, write x2 and bf16 hi/lo split
// ---------------------------------------------------------------------------
__global__ __launch_bounds__(256) void proj_split_kernel(const float* __restrict__ x) {
    const int b = blockIdx.x;
    const float* xr = x + (size_t)b * DDIM;
    const int tid = threadIdx.x;

    float v[4];
    float s = 0.f;
    #pragma unroll
    for (int i = 0; i < 4; i++) { v[i] = xr[tid + i * 256]; s += v[i] * v[i]; }
    #pragma unroll
    for (int o = 16; o > 0; o >>= 1) s += __shfl_xor_sync(0xFFFFFFFFu, s, o);
    __shared__ float red[8];
    if ((tid & 31) == 0) red[tid >> 5] = s;
    __syncthreads();
    __shared__ float sh_scale;
    if (tid == 0) {
        float tot = 0.f;
        #pragma unroll
        for (int w = 0; w < 8; w++) tot += red[w];
        float xn = fmaxf(sqrtf(tot), EPSV);
        float scale = (xn > MAXN) ? (MAXN / xn) : 1.0f;
        sh_scale = scale;
        g_x2[b] = tot * scale * scale;
    }
    __syncthreads();
    const float sc = sh_scale;
    #pragma unroll
    for (int i = 0; i < 4; i++) {
        const int idx = tid + i * 256;
        float xv = v[i] * sc;
        __nv_bfloat16 hi = __float2bfloat16(xv);
        float lo = xv - __bfloat162float(hi);
        g_xhi[(size_t)b * DDIM + idx] = hi;
        g_xlo[(size_t)b * DDIM + idx] = __float2bfloat16(lo);
    }
}

// ---------------------------------------------------------------------------
// Kernel 2: per-class stats + bf16 hi/lo split for p and a
// ---------------------------------------------------------------------------
__global__ __launch_bounds__(256) void stats_split_kernel(const float* __restrict__ a,
                                                          const float* __restrict__ p) {
    const int c = blockIdx.x;
    const float* ar = a + (size_t)c * DDIM;
    const float* pr = p + (size_t)c * DDIM;
    const int tid = threadIdx.x;

    float sp2 = 0.f, spa = 0.f, sa2 = 0.f;
    #pragma unroll
    for (int i = 0; i < 4; i++) {
        const int idx = tid + i * 256;
        float av = ar[idx], pv = pr[idx];
        sp2 += pv * pv; spa += pv * av; sa2 += av * av;

        __nv_bfloat16 ph = __float2bfloat16(pv);
        g_phi[(size_t)c * DDIM + idx] = ph;
        g_plo[(size_t)c * DDIM + idx] = __float2bfloat16(pv - __bfloat162float(ph));
        __nv_bfloat16 ah = __float2bfloat16(av);
        g_ahi[(size_t)c * DDIM + idx] = ah;
        g_alo[(size_t)c * DDIM + idx] = __float2bfloat16(av - __bfloat162float(ah));
    }
    #pragma unroll
    for (int o = 16; o > 0; o >>= 1) {
        sp2 += __shfl_xor_sync(0xFFFFFFFFu, sp2, o);
        spa += __shfl_xor_sync(0xFFFFFFFFu, spa, o);
        sa2 += __shfl_xor_sync(0xFFFFFFFFu, sa2, o);
    }
    __shared__ float r0[8], r1[8], r2[8];
    if ((tid & 31) == 0) { r0[tid >> 5] = sp2; r1[tid >> 5] = spa; r2[tid >> 5] = sa2; }
    __syncthreads();
    if (tid == 0) {
        float t0 = 0.f, t1 = 0.f, t2 = 0.f;
        #pragma unroll
        for (int w = 0; w < 8; w++) { t0 += r0[w]; t1 += r1[w]; t2 += r2[w]; }
        g_p2[c] = t0; g_pa[c] = t1; g_an[c] = sqrtf(t2);
    }
}

// ---------------------------------------------------------------------------
// Epilogue math: 1 MUFU (rsqrt), no division, no log.
//   q = N/D with N = 2*u*den, D = (den^2 + w)*an  (D > 0, |q| <= 1)
//   z = q/sqrt(1+q^2) = N/sqrt(N^2+D^2) = tanh(asinh(q)),  |z| <= ~0.708
//   asinh(q) = atanh(z) = z * sum_{k=0..12} z^(2k)/(2k+1)   (tail < 7e-6 rel)
// ---------------------------------------------------------------------------
__device__ __forceinline__ float hyp_logit(float px, float xa, float x2,
                                           float p2, float pa, float an) {
    const float A   = 1.0f - 2.0f * px + x2;
    const float Bc  = 1.0f - p2;
    const float den = fmaxf(fmaf(x2, p2, fmaf(-2.0f, px, 1.0f)), EPSV);
    const float w   = fmaxf(fmaf(A * A, p2, fmaf(Bc * Bc, x2, -2.0f * A * Bc * px)), 0.0f);
    const float u   = fmaf(Bc, xa, -A * pa);
    const float N   = 2.0f * u * den;
    const float D   = fmaf(den, den, w) * an;
    const float z   = N * rsqrtf(fmaf(N, N, D * D));
    const float t   = z * z;
    float s = 1.0f / 25.0f;
    s = fmaf(s, t, 1.0f / 23.0f); s = fmaf(s, t, 1.0f / 21.0f);
    s = fmaf(s, t, 1.0f / 19.0f); s = fmaf(s, t, 1.0f / 17.0f);
    s = fmaf(s, t, 1.0f / 15.0f); s = fmaf(s, t, 1.0f / 13.0f);
    s = fmaf(s, t, 1.0f / 11.0f); s = fmaf(s, t, 1.0f / 9.0f);
    s = fmaf(s, t, 1.0f / 7.0f);  s = fmaf(s, t, 1.0f / 5.0f);
    s = fmaf(s, t, 1.0f / 3.0f);  s = fmaf(s, t, 1.0f);
    return -z * s;
}

// ---------------------------------------------------------------------------
// Kernel 3: dual split-bf16 GEMM via mma.sync (HMMA) + fused epilogue
//   CTA: 128(batch) x 128(class), BK=32, 512 threads (16 warps, 4x4).
//   Warp tile 32x32 per GEMM. 3 split products per GEMM: hh + hl + lh.
// ---------------------------------------------------------------------------
#define BM 128
#define BN 128
#define BK 32
#define NKIT (DDIM / BK)          // 32
#define ROWB 80                   // smem bytes/row: 64 data + 16 pad (conflict-free)
#define TILEB (128 * ROWB)        // 10240
#define STAGEB (6 * TILEB)        // 61440
#define SMEM_NEED (2 * STAGEB)    // 122880

__global__ __launch_bounds__(512, 1) void mlr_mma_kernel(float* __restrict__ out) {
    extern __shared__ char sm[];
    const uint32_t sb = smem_u32(sm);
    const int tid  = threadIdx.x;
    const int wid  = tid >> 5;
    const int lane = tid & 31;
    const int wm = wid & 3;        // warp row (batch),  4 warps
    const int wn = wid >> 2;       // warp col (class),  4 warps
    const int cb = blockIdx.x * BN;
    const int rb = blockIdx.y * BM;

    const __nv_bfloat16* srcs[6] = {
        g_xhi + (size_t)rb * DDIM, g_xlo + (size_t)rb * DDIM,
        g_phi + (size_t)cb * DDIM, g_plo + (size_t)cb * DDIM,
        g_ahi + (size_t)cb * DDIM, g_alo + (size_t)cb * DDIM
    };

    // cp.async mapping: 512 threads -> 128 rows x 4 chunks of 16B
    const int lrow = tid >> 2;
    const int lch  = tid & 3;
    const uint32_t dst0 = sb + lrow * ROWB + lch * 16;
    const size_t   soff = (size_t)lrow * DDIM + lch * 8;

    // ldmatrix lane mappings
    const int a_r = lane & 15;                       // A: row within m16
    const int a_c = lane >> 4;                       //    which 8-col half
    const int b_r = (lane & 7) | ((lane & 16) >> 1); // B: row within n16
    const int b_h = (lane >> 3) & 1;                 //    which k-half
    const uint32_t sA  = (wm * 32 + a_r) * ROWB + a_c * 16;
    const uint32_t sB0 = (wn * 32 + b_r) * ROWB + b_h * 16;

    float cP[2][4][4];
    float cA[2][4][4];
    #pragma unroll
    for (int mt = 0; mt < 2; mt++)
        #pragma unroll
        for (int nt = 0; nt < 4; nt++)
            #pragma unroll
            for (int i = 0; i < 4; i++) { cP[mt][nt][i] = 0.f; cA[mt][nt][i] = 0.f; }

    // prologue: stages 0 and 1
    #pragma unroll
    for (int s = 0; s < 2; s++) {
        #pragma unroll
        for (int t = 0; t < 6; t++)
            CP_ASYNC16(dst0 + s * STAGEB + t * TILEB, srcs[t] + soff + s * BK);
        asm volatile("cp.async.commit_group;" ::: "memory");
    }

    for (int k = 0; k < NKIT; k++) {
        asm volatile("cp.async.wait_group 1;" ::: "memory");
        __syncthreads();
        const uint32_t st = sb + (k & 1) * STAGEB;

        #pragma unroll
        for (int ks = 0; ks < 2; ks++) {
            const uint32_t kofs = ks * 32;   // 16 bf16 = 32 bytes
            uint32_t xh[2][4], xl[2][4];
            #pragma unroll
            for (int mt = 0; mt < 2; mt++) {
                LDSM4(xh[mt], st + 0 * TILEB + sA + mt * 16 * ROWB + kofs);
                LDSM4(xl[mt], st + 1 * TILEB + sA + mt * 16 * ROWB + kofs);
            }
            uint32_t bb[2][4];
            // --- p_hi: hh + lh into P ---
            LDSM4(bb[0], st + 2 * TILEB + sB0 + kofs);
            LDSM4(bb[1], st + 2 * TILEB + sB0 + 16 * ROWB + kofs);
            #pragma unroll
            for (int mt = 0; mt < 2; mt++)
                #pragma unroll
                for (int nt = 0; nt < 4; nt++) {
                    MMA16816(cP[mt][nt], xh[mt], bb[nt >> 1][(nt & 1) * 2], bb[nt >> 1][(nt & 1) * 2 + 1]);
                    MMA16816(cP[mt][nt], xl[mt], bb[nt >> 1][(nt & 1) * 2], bb[nt >> 1][(nt & 1) * 2 + 1]);
                }
            // --- p_lo: hl into P ---
            LDSM4(bb[0], st + 3 * TILEB + sB0 + kofs);
            LDSM4(bb[1], st + 3 * TILEB + sB0 + 16 * ROWB + kofs);
            #pragma unroll
            for (int mt = 0; mt < 2; mt++)
                #pragma unroll
                for (int nt = 0; nt < 4; nt++)
                    MMA16816(cP[mt][nt], xh[mt], bb[nt >> 1][(nt & 1) * 2], bb[nt >> 1][(nt & 1) * 2 + 1]);
            // --- a_hi: hh + lh into A ---
            LDSM4(bb[0], st + 4 * TILEB + sB0 + kofs);
            LDSM4(bb[1], st + 4 * TILEB + sB0 + 16 * ROWB + kofs);
            #pragma unroll
            for (int mt = 0; mt < 2; mt++)
                #pragma unroll
                for (int nt = 0; nt < 4; nt++) {
                    MMA16816(cA[mt][nt], xh[mt], bb[nt >> 1][(nt & 1) * 2], bb[nt >> 1][(nt & 1) * 2 + 1]);
                    MMA16816(cA[mt][nt], xl[mt], bb[nt >> 1][(nt & 1) * 2], bb[nt >> 1][(nt & 1) * 2 + 1]);
                }
            // --- a_lo: hl into A ---
            LDSM4(bb[0], st + 5 * TILEB + sB0 + kofs);
            LDSM4(bb[1], st + 5 * TILEB + sB0 + 16 * ROWB + kofs);
            #pragma unroll
            for (int mt = 0; mt < 2; mt++)
                #pragma unroll
                for (int nt = 0; nt < 4; nt++)
                    MMA16816(cA[mt][nt], xh[mt], bb[nt >> 1][(nt & 1) * 2], bb[nt >> 1][(nt & 1) * 2 + 1]);
        }

        __syncthreads();
        if (k + 2 < NKIT) {
            #pragma unroll
            for (int t = 0; t < 6; t++)
                CP_ASYNC16(dst0 + (k & 1) * STAGEB + t * TILEB,
                           srcs[t] + soff + (size_t)(k + 2) * BK);
        }
        asm volatile("cp.async.commit_group;" ::: "memory");
    }

    // epilogue: fragment layout c0,c1 = (row g, cols tg*2..+1); c2,c3 = row g+8
    const int g  = lane >> 2;
    const int tg = lane & 3;
    #pragma unroll
    for (int mt = 0; mt < 2; mt++) {
        #pragma unroll
        for (int h = 0; h < 2; h++) {
            const int row = rb + wm * 32 + mt * 16 + h * 8 + g;
            const float x2 = g_x2[row];
            float* orow = out + (size_t)row * CDIM + cb + wn * 32;
            #pragma unroll
            for (int nt = 0; nt < 4; nt++) {
                const int col = cb + wn * 32 + nt * 8 + tg * 2;
                float2 r;
                r.x = hyp_logit(cP[mt][nt][2 * h],     cA[mt][nt][2 * h],     x2,
                                g_p2[col],     g_pa[col],     g_an[col]);
                r.y = hyp_logit(cP[mt][nt][2 * h + 1], cA[mt][nt][2 * h + 1], x2,
                                g_p2[col + 1], g_pa[col + 1], g_an[col + 1]);
                *(float2*)(orow + nt * 8 + tg * 2) = r;
            }
        }
    }
}

// ---------------------------------------------------------------------------
extern "C" void kernel_launch(void* const* d_in, const int* in_sizes, int n_in,
                              void* d_out, int out_size) {
    const float* x = (const float*)d_in[0];
    const float* a = (const float*)d_in[1];
    const float* p = (const float*)d_in[2];
    float* out = (float*)d_out;

    cudaFuncSetAttribute(mlr_mma_kernel,
                         cudaFuncAttributeMaxDynamicSharedMemorySize, SMEM_NEED);

    proj_split_kernel<<<BDIM, 256>>>(x);
    stats_split_kernel<<<CDIM, 256>>>(a, p);
    dim3 grid(CDIM / BN, BDIM / BM);
    mlr_mma_kernel<<<grid, 512, SMEM_NEED>>>(out);
}

// round 4
// speedup vs baseline: 3.8639x; 1.3367x over previous
#include <cuda_runtime.h>
#include <cuda_bf16.h>
#include <math.h>
#include <cstdint>

// Fixed shapes for HyperbolicMLR_33045478375870
#define BDIM 4096
#define DDIM 1024
#define CDIM 4096
#define EPSV 1e-15f
#define MAXN 0.99999f   // (1 - 1e-5)/sqrt(c), c = 1

// ---------------------------------------------------------------------------
// Device scratch (no allocations allowed)
// ---------------------------------------------------------------------------
__device__ __nv_bfloat16 g_xhi[(size_t)BDIM * DDIM];
__device__ __nv_bfloat16 g_phi[(size_t)CDIM * DDIM];
__device__ __nv_bfloat16 g_plo[(size_t)CDIM * DDIM];
__device__ __nv_bfloat16 g_ahi[(size_t)CDIM * DDIM];
__device__ __nv_bfloat16 g_alo[(size_t)CDIM * DDIM];
__device__ float g_x2[BDIM];
__device__ float g_p2[CDIM];
__device__ float g_pa[CDIM];
__device__ float g_an[CDIM];

// ---------------------------------------------------------------------------
__device__ __forceinline__ uint32_t smem_u32(const void* p) {
    uint32_t a;
    asm("{ .reg .u64 t; cvta.to.shared.u64 t, %1; cvt.u32.u64 %0, t; }"
        : "=r"(a) : "l"(p));
    return a;
}

#define LDSM4(r, addr) \
    asm volatile("ldmatrix.sync.aligned.m8n8.x4.shared.b16 {%0,%1,%2,%3}, [%4];" \
                 : "=r"((r)[0]), "=r"((r)[1]), "=r"((r)[2]), "=r"((r)[3]) \
                 : "r"(addr))

#define MMA16816(c, a, b0, b1) \
    asm volatile("mma.sync.aligned.m16n8k16.row.col.f32.bf16.bf16.f32 " \
                 "{%0,%1,%2,%3},{%4,%5,%6,%7},{%8,%9},{%0,%1,%2,%3};" \
                 : "+f"((c)[0]), "+f"((c)[1]), "+f"((c)[2]), "+f"((c)[3]) \
                 : "r"((a)[0]), "r"((a)[1]), "r"((a)[2]), "r"((a)[3]), \
                   "r"(b0), "r"(b1))

#define CP_ASYNC16(dst, src) \
    asm volatile("cp.async.cg.shared.global [%0], [%1], 16;" \
                 :: "r"(dst), "l"(__cvta_generic_to_global(src)))

// ---------------------------------------------------------------------------
// Kernel 1: project x onto the ball, write x2 and bf16 x_hi
// ---------------------------------------------------------------------------
__global__ __launch_bounds__(256) void proj_split_kernel(const float* __restrict__ x) {
    const int b = blockIdx.x;
    const float* xr = x + (size_t)b * DDIM;
    const int tid = threadIdx.x;

    float v[4];
    float s = 0.f;
    #pragma unroll
    for (int i = 0; i < 4; i++) { v[i] = xr[tid + i * 256]; s += v[i] * v[i]; }
    #pragma unroll
    for (int o = 16; o > 0; o >>= 1) s += __shfl_xor_sync(0xFFFFFFFFu, s, o);
    __shared__ float red[8];
    if ((tid & 31) == 0) red[tid >> 5] = s;
    __syncthreads();
    __shared__ float sh_scale;
    if (tid == 0) {
        float tot = 0.f;
        #pragma unroll
        for (int w = 0; w < 8; w++) tot += red[w];
        float xn = fmaxf(sqrtf(tot), EPSV);
        float scale = (xn > MAXN) ? (MAXN / xn) : 1.0f;
        sh_scale = scale;
        g_x2[b] = tot * scale * scale;
    }
    __syncthreads();
    const float sc = sh_scale;
    #pragma unroll
    for (int i = 0; i < 4; i++) {
        const int idx = tid + i * 256;
        g_xhi[(size_t)b * DDIM + idx] = __float2bfloat16(v[i] * sc);
    }
}

// ---------------------------------------------------------------------------
// Kernel 2: per-class stats + bf16 hi/lo split for p and a
// ---------------------------------------------------------------------------
__global__ __launch_bounds__(256) void stats_split_kernel(const float* __restrict__ a,
                                                          const float* __restrict__ p) {
    const int c = blockIdx.x;
    const float* ar = a + (size_t)c * DDIM;
    const float* pr = p + (size_t)c * DDIM;
    const int tid = threadIdx.x;

    float sp2 = 0.f, spa = 0.f, sa2 = 0.f;
    #pragma unroll
    for (int i = 0; i < 4; i++) {
        const int idx = tid + i * 256;
        float av = ar[idx], pv = pr[idx];
        sp2 += pv * pv; spa += pv * av; sa2 += av * av;

        __nv_bfloat16 ph = __float2bfloat16(pv);
        g_phi[(size_t)c * DDIM + idx] = ph;
        g_plo[(size_t)c * DDIM + idx] = __float2bfloat16(pv - __bfloat162float(ph));
        __nv_bfloat16 ah = __float2bfloat16(av);
        g_ahi[(size_t)c * DDIM + idx] = ah;
        g_alo[(size_t)c * DDIM + idx] = __float2bfloat16(av - __bfloat162float(ah));
    }
    #pragma unroll
    for (int o = 16; o > 0; o >>= 1) {
        sp2 += __shfl_xor_sync(0xFFFFFFFFu, sp2, o);
        spa += __shfl_xor_sync(0xFFFFFFFFu, spa, o);
        sa2 += __shfl_xor_sync(0xFFFFFFFFu, sa2, o);
    }
    __shared__ float r0[8], r1[8], r2[8];
    if ((tid & 31) == 0) { r0[tid >> 5] = sp2; r1[tid >> 5] = spa; r2[tid >> 5] = sa2; }
    __syncthreads();
    if (tid == 0) {
        float t0 = 0.f, t1 = 0.f, t2 = 0.f;
        #pragma unroll
        for (int w = 0; w < 8; w++) { t0 += r0[w]; t1 += r1[w]; t2 += r2[w]; }
        g_p2[c] = t0; g_pa[c] = t1; g_an[c] = sqrtf(t2);
    }
}

// ---------------------------------------------------------------------------
// Epilogue math: 1 MUFU (rsqrt), no division, no log.
// ---------------------------------------------------------------------------
__device__ __forceinline__ float hyp_logit(float px, float xa, float x2,
                                           float p2, float pa, float an) {
    const float A   = 1.0f - 2.0f * px + x2;
    const float Bc  = 1.0f - p2;
    const float den = fmaxf(fmaf(x2, p2, fmaf(-2.0f, px, 1.0f)), EPSV);
    const float w   = fmaxf(fmaf(A * A, p2, fmaf(Bc * Bc, x2, -2.0f * A * Bc * px)), 0.0f);
    const float u   = fmaf(Bc, xa, -A * pa);
    const float N   = 2.0f * u * den;
    const float D   = fmaf(den, den, w) * an;
    const float z   = N * rsqrtf(fmaf(N, N, D * D));
    const float t   = z * z;
    float s = 1.0f / 25.0f;
    s = fmaf(s, t, 1.0f / 23.0f); s = fmaf(s, t, 1.0f / 21.0f);
    s = fmaf(s, t, 1.0f / 19.0f); s = fmaf(s, t, 1.0f / 17.0f);
    s = fmaf(s, t, 1.0f / 15.0f); s = fmaf(s, t, 1.0f / 13.0f);
    s = fmaf(s, t, 1.0f / 11.0f); s = fmaf(s, t, 1.0f / 9.0f);
    s = fmaf(s, t, 1.0f / 7.0f);  s = fmaf(s, t, 1.0f / 5.0f);
    s = fmaf(s, t, 1.0f / 3.0f);  s = fmaf(s, t, 1.0f);
    return -z * s;
}

// ---------------------------------------------------------------------------
// Kernel 3: dual 4-chain bf16 GEMM via mma.sync + fused epilogue
//   CTA 128x128, 256 threads (8 warps: 2 m-rows x 4 n-cols), warp tile 64x32.
//   Chains: P = xh*ph + xh*pl;  A = xh*ah + xh*al.
//   4-stage cp.async pipeline, BK=32, 5 smem tiles/stage.
// ---------------------------------------------------------------------------
#define BM 128
#define BN 128
#define BK 32
#define NKIT (DDIM / BK)          // 32
#define NSTG 4
#define ROWB 80                   // 64 data + 16 pad
#define TILEB (128 * ROWB)        // 10240
#define STAGEB (5 * TILEB)        // 51200
#define SMEM_NEED (NSTG * STAGEB) // 204800

__global__ __launch_bounds__(256, 1) void mlr_mma_kernel(float* __restrict__ out) {
    extern __shared__ char sm[];
    const uint32_t sb = smem_u32(sm);
    const int tid  = threadIdx.x;
    const int wid  = tid >> 5;
    const int lane = tid & 31;
    const int wn = wid & 3;        // warp col (class):  4 x 32
    const int wm = wid >> 2;       // warp row (batch):  2 x 64
    const int cb = blockIdx.x * BN;
    const int rb = blockIdx.y * BM;

    const __nv_bfloat16* srcs[5] = {
        g_xhi + (size_t)rb * DDIM,
        g_phi + (size_t)cb * DDIM, g_plo + (size_t)cb * DDIM,
        g_ahi + (size_t)cb * DDIM, g_alo + (size_t)cb * DDIM
    };

    // cp.async mapping: 256 threads x 2 iters -> 128 rows x 4 chunks (16B)
    const int r0_ = tid >> 2, c0_ = tid & 3;
    const int r1_ = (tid + 256) >> 2, c1_ = (tid + 256) & 3;
    const uint32_t d0 = r0_ * ROWB + c0_ * 16;
    const uint32_t d1 = r1_ * ROWB + c1_ * 16;
    const size_t s0 = (size_t)r0_ * DDIM + c0_ * 8;
    const size_t s1 = (size_t)r1_ * DDIM + c1_ * 8;

    // ldmatrix lane mappings
    const int a_r = lane & 15;
    const int a_c = lane >> 4;
    const int b_r = (lane & 7) | ((lane & 16) >> 1);
    const int b_h = (lane >> 3) & 1;
    const uint32_t sA  = (wm * 64 + a_r) * ROWB + a_c * 16;
    const uint32_t sB0 = (wn * 32 + b_r) * ROWB + b_h * 16;

    float cP[4][4][4];
    float cA[4][4][4];
    #pragma unroll
    for (int mt = 0; mt < 4; mt++)
        #pragma unroll
        for (int nt = 0; nt < 4; nt++)
            #pragma unroll
            for (int i = 0; i < 4; i++) { cP[mt][nt][i] = 0.f; cA[mt][nt][i] = 0.f; }

    // prologue: stages 0..2
    #pragma unroll
    for (int s = 0; s < NSTG - 1; s++) {
        const uint32_t db = sb + s * STAGEB;
        const size_t ko = (size_t)s * BK;
        #pragma unroll
        for (int t = 0; t < 5; t++) {
            CP_ASYNC16(db + t * TILEB + d0, srcs[t] + s0 + ko);
            CP_ASYNC16(db + t * TILEB + d1, srcs[t] + s1 + ko);
        }
        asm volatile("cp.async.commit_group;" ::: "memory");
    }

    for (int k = 0; k < NKIT; k++) {
        asm volatile("cp.async.wait_group %0;" :: "n"(NSTG - 2) : "memory");
        __syncthreads();

        // issue loads for stage k+3 into slot (k+3)&3 (frees slot used at k-1)
        if (k + NSTG - 1 < NKIT) {
            const uint32_t db = sb + ((k + NSTG - 1) & (NSTG - 1)) * STAGEB;
            const size_t ko = (size_t)(k + NSTG - 1) * BK;
            #pragma unroll
            for (int t = 0; t < 5; t++) {
                CP_ASYNC16(db + t * TILEB + d0, srcs[t] + s0 + ko);
                CP_ASYNC16(db + t * TILEB + d1, srcs[t] + s1 + ko);
            }
        }
        asm volatile("cp.async.commit_group;" ::: "memory");

        const uint32_t st = sb + (k & (NSTG - 1)) * STAGEB;
        #pragma unroll
        for (int ks = 0; ks < 2; ks++) {
            const uint32_t kofs = ks * 32;
            uint32_t xh[4][4];
            #pragma unroll
            for (int mt = 0; mt < 4; mt++)
                LDSM4(xh[mt], st + 0 * TILEB + sA + mt * 16 * ROWB + kofs);

            uint32_t bb[2][4];
            // ph -> P
            LDSM4(bb[0], st + 1 * TILEB + sB0 + kofs);
            LDSM4(bb[1], st + 1 * TILEB + sB0 + 16 * ROWB + kofs);
            #pragma unroll
            for (int mt = 0; mt < 4; mt++)
                #pragma unroll
                for (int nt = 0; nt < 4; nt++)
                    MMA16816(cP[mt][nt], xh[mt], bb[nt >> 1][(nt & 1) * 2], bb[nt >> 1][(nt & 1) * 2 + 1]);
            // pl -> P
            LDSM4(bb[0], st + 2 * TILEB + sB0 + kofs);
            LDSM4(bb[1], st + 2 * TILEB + sB0 + 16 * ROWB + kofs);
            #pragma unroll
            for (int mt = 0; mt < 4; mt++)
                #pragma unroll
                for (int nt = 0; nt < 4; nt++)
                    MMA16816(cP[mt][nt], xh[mt], bb[nt >> 1][(nt & 1) * 2], bb[nt >> 1][(nt & 1) * 2 + 1]);
            // ah -> A
            LDSM4(bb[0], st + 3 * TILEB + sB0 + kofs);
            LDSM4(bb[1], st + 3 * TILEB + sB0 + 16 * ROWB + kofs);
            #pragma unroll
            for (int mt = 0; mt < 4; mt++)
                #pragma unroll
                for (int nt = 0; nt < 4; nt++)
                    MMA16816(cA[mt][nt], xh[mt], bb[nt >> 1][(nt & 1) * 2], bb[nt >> 1][(nt & 1) * 2 + 1]);
            // al -> A
            LDSM4(bb[0], st + 4 * TILEB + sB0 + kofs);
            LDSM4(bb[1], st + 4 * TILEB + sB0 + 16 * ROWB + kofs);
            #pragma unroll
            for (int mt = 0; mt < 4; mt++)
                #pragma unroll
                for (int nt = 0; nt < 4; nt++)
                    MMA16816(cA[mt][nt], xh[mt], bb[nt >> 1][(nt & 1) * 2], bb[nt >> 1][(nt & 1) * 2 + 1]);
        }
    }

    // epilogue
    const int g  = lane >> 2;
    const int tg = lane & 3;
    #pragma unroll
    for (int mt = 0; mt < 4; mt++) {
        #pragma unroll
        for (int h = 0; h < 2; h++) {
            const int row = rb + wm * 64 + mt * 16 + h * 8 + g;
            const float x2 = g_x2[row];
            float* orow = out + (size_t)row * CDIM + cb + wn * 32;
            #pragma unroll
            for (int nt = 0; nt < 4; nt++) {
                const int col = cb + wn * 32 + nt * 8 + tg * 2;
                float2 r;
                r.x = hyp_logit(cP[mt][nt][2 * h],     cA[mt][nt][2 * h],     x2,
                                g_p2[col],     g_pa[col],     g_an[col]);
                r.y = hyp_logit(cP[mt][nt][2 * h + 1], cA[mt][nt][2 * h + 1], x2,
                                g_p2[col + 1], g_pa[col + 1], g_an[col + 1]);
                *(float2*)(orow + nt * 8 + tg * 2) = r;
            }
        }
    }
}

// ---------------------------------------------------------------------------
extern "C" void kernel_launch(void* const* d_in, const int* in_sizes, int n_in,
                              void* d_out, int out_size) {
    const float* x = (const float*)d_in[0];
    const float* a = (const float*)d_in[1];
    const float* p = (const float*)d_in[2];
    float* out = (float*)d_out;

    cudaFuncSetAttribute(mlr_mma_kernel,
                         cudaFuncAttributeMaxDynamicSharedMemorySize, SMEM_NEED);

    proj_split_kernel<<<BDIM, 256>>>(x);
    stats_split_kernel<<<CDIM, 256>>>(a, p);
    dim3 grid(CDIM / BN, BDIM / BM);
    mlr_mma_kernel<<<grid, 256, SMEM_NEED>>>(out);
}

// round 5
// speedup vs baseline: 7.7401x; 2.0032x over previous
#include <cuda_runtime.h>
#include <cuda_bf16.h>
#include <math.h>
#include <cstdint>

// Fixed shapes for HyperbolicMLR_33045478375870
#define BDIM 4096
#define DDIM 1024
#define CDIM 4096
#define EPSV 1e-15f
#define MAXN 0.99999f   // (1 - 1e-5)/sqrt(c), c = 1

// ---------------------------------------------------------------------------
// Device scratch (no allocations allowed)
// ---------------------------------------------------------------------------
__device__ __nv_bfloat16 g_xhi[(size_t)BDIM * DDIM];
__device__ __nv_bfloat16 g_phi[(size_t)CDIM * DDIM];
__device__ __nv_bfloat16 g_ahi[(size_t)CDIM * DDIM];
__device__ float g_x2[BDIM];
__device__ float g_p2[CDIM];
__device__ float g_pa[CDIM];
__device__ float g_an[CDIM];

// ---------------------------------------------------------------------------
__device__ __forceinline__ uint32_t smem_u32(const void* p) {
    uint32_t a;
    asm("{ .reg .u64 t; cvta.to.shared.u64 t, %1; cvt.u32.u64 %0, t; }"
        : "=r"(a) : "l"(p));
    return a;
}

#define LDSM4(r, addr) \
    asm volatile("ldmatrix.sync.aligned.m8n8.x4.shared.b16 {%0,%1,%2,%3}, [%4];" \
                 : "=r"((r)[0]), "=r"((r)[1]), "=r"((r)[2]), "=r"((r)[3]) \
                 : "r"(addr))

#define MMA16816(c, a, b0, b1) \
    asm volatile("mma.sync.aligned.m16n8k16.row.col.f32.bf16.bf16.f32 " \
                 "{%0,%1,%2,%3},{%4,%5,%6,%7},{%8,%9},{%0,%1,%2,%3};" \
                 : "+f"((c)[0]), "+f"((c)[1]), "+f"((c)[2]), "+f"((c)[3]) \
                 : "r"((a)[0]), "r"((a)[1]), "r"((a)[2]), "r"((a)[3]), \
                   "r"(b0), "r"(b1))

#define CP_ASYNC16(dst, src) \
    asm volatile("cp.async.cg.shared.global [%0], [%1], 16;" \
                 :: "r"(dst), "l"(__cvta_generic_to_global(src)))

// ---------------------------------------------------------------------------
// Kernel 1: project x onto the ball, write x2 and bf16 x_hi
// ---------------------------------------------------------------------------
__global__ __launch_bounds__(256) void proj_split_kernel(const float* __restrict__ x) {
    const int b = blockIdx.x;
    const float* xr = x + (size_t)b * DDIM;
    const int tid = threadIdx.x;

    float v[4];
    float s = 0.f;
    #pragma unroll
    for (int i = 0; i < 4; i++) { v[i] = xr[tid + i * 256]; s += v[i] * v[i]; }
    #pragma unroll
    for (int o = 16; o > 0; o >>= 1) s += __shfl_xor_sync(0xFFFFFFFFu, s, o);
    __shared__ float red[8];
    if ((tid & 31) == 0) red[tid >> 5] = s;
    __syncthreads();
    __shared__ float sh_scale;
    if (tid == 0) {
        float tot = 0.f;
        #pragma unroll
        for (int w = 0; w < 8; w++) tot += red[w];
        float xn = fmaxf(sqrtf(tot), EPSV);
        float scale = (xn > MAXN) ? (MAXN / xn) : 1.0f;
        sh_scale = scale;
        g_x2[b] = tot * scale * scale;
    }
    __syncthreads();
    const float sc = sh_scale;
    #pragma unroll
    for (int i = 0; i < 4; i++) {
        const int idx = tid + i * 256;
        g_xhi[(size_t)b * DDIM + idx] = __float2bfloat16(v[i] * sc);
    }
}

// ---------------------------------------------------------------------------
// Kernel 2: per-class stats + bf16 casts of p and a
// ---------------------------------------------------------------------------
__global__ __launch_bounds__(256) void stats_split_kernel(const float* __restrict__ a,
                                                          const float* __restrict__ p) {
    const int c = blockIdx.x;
    const float* ar = a + (size_t)c * DDIM;
    const float* pr = p + (size_t)c * DDIM;
    const int tid = threadIdx.x;

    float sp2 = 0.f, spa = 0.f, sa2 = 0.f;
    #pragma unroll
    for (int i = 0; i < 4; i++) {
        const int idx = tid + i * 256;
        float av = ar[idx], pv = pr[idx];
        sp2 += pv * pv; spa += pv * av; sa2 += av * av;
        g_phi[(size_t)c * DDIM + idx] = __float2bfloat16(pv);
        g_ahi[(size_t)c * DDIM + idx] = __float2bfloat16(av);
    }
    #pragma unroll
    for (int o = 16; o > 0; o >>= 1) {
        sp2 += __shfl_xor_sync(0xFFFFFFFFu, sp2, o);
        spa += __shfl_xor_sync(0xFFFFFFFFu, spa, o);
        sa2 += __shfl_xor_sync(0xFFFFFFFFu, sa2, o);
    }
    __shared__ float r0[8], r1[8], r2[8];
    if ((tid & 31) == 0) { r0[tid >> 5] = sp2; r1[tid >> 5] = spa; r2[tid >> 5] = sa2; }
    __syncthreads();
    if (tid == 0) {
        float t0 = 0.f, t1 = 0.f, t2 = 0.f;
        #pragma unroll
        for (int w = 0; w < 8; w++) { t0 += r0[w]; t1 += r1[w]; t2 += r2[w]; }
        g_p2[c] = t0; g_pa[c] = t1; g_an[c] = sqrtf(t2);
    }
}

// ---------------------------------------------------------------------------
// Epilogue math: 1 MUFU (rsqrt), no division, no log.
// ---------------------------------------------------------------------------
__device__ __forceinline__ float hyp_logit(float px, float xa, float x2,
                                           float p2, float pa, float an) {
    const float A   = 1.0f - 2.0f * px + x2;
    const float Bc  = 1.0f - p2;
    const float den = fmaxf(fmaf(x2, p2, fmaf(-2.0f, px, 1.0f)), EPSV);
    const float w   = fmaxf(fmaf(A * A, p2, fmaf(Bc * Bc, x2, -2.0f * A * Bc * px)), 0.0f);
    const float u   = fmaf(Bc, xa, -A * pa);
    const float N   = 2.0f * u * den;
    const float D   = fmaf(den, den, w) * an;
    const float z   = N * rsqrtf(fmaf(N, N, D * D));
    const float t   = z * z;
    float s = 1.0f / 25.0f;
    s = fmaf(s, t, 1.0f / 23.0f); s = fmaf(s, t, 1.0f / 21.0f);
    s = fmaf(s, t, 1.0f / 19.0f); s = fmaf(s, t, 1.0f / 17.0f);
    s = fmaf(s, t, 1.0f / 15.0f); s = fmaf(s, t, 1.0f / 13.0f);
    s = fmaf(s, t, 1.0f / 11.0f); s = fmaf(s, t, 1.0f / 9.0f);
    s = fmaf(s, t, 1.0f / 7.0f);  s = fmaf(s, t, 1.0f / 5.0f);
    s = fmaf(s, t, 1.0f / 3.0f);  s = fmaf(s, t, 1.0f);
    return -z * s;
}

// ---------------------------------------------------------------------------
// Kernel 3: dual pure-bf16 GEMM via mma.sync + fused epilogue
//   CTA 128x128, 512 threads (16 warps: 2 m x 8 n), warp tile 64x16.
//   Chains: P = xh*ph;  A = xh*ah.
//   4-stage cp.async pipeline, BK=32, 3 smem tiles/stage.
// ---------------------------------------------------------------------------
#define BM 128
#define BN 128
#define BK 32
#define NKIT (DDIM / BK)          // 32
#define NSTG 4
#define ROWB 80                   // 64 data + 16 pad
#define TILEB (128 * ROWB)        // 10240
#define STAGEB (3 * TILEB)        // 30720
#define SMEM_NEED (NSTG * STAGEB) // 122880

__global__ __launch_bounds__(512, 1) void mlr_mma_kernel(float* __restrict__ out) {
    extern __shared__ char sm[];
    const uint32_t sb = smem_u32(sm);
    const int tid  = threadIdx.x;
    const int wid  = tid >> 5;
    const int lane = tid & 31;
    const int wn = wid & 7;        // warp col (class):  8 x 16
    const int wm = wid >> 3;       // warp row (batch):  2 x 64
    const int cb = blockIdx.x * BN;
    const int rb = blockIdx.y * BM;

    const __nv_bfloat16* srcs[3] = {
        g_xhi + (size_t)rb * DDIM,
        g_phi + (size_t)cb * DDIM,
        g_ahi + (size_t)cb * DDIM
    };

    // cp.async mapping: 512 threads -> 128 rows x 4 chunks (16B each) per tile
    const int lrow = tid >> 2, lch = tid & 3;
    const uint32_t d0 = lrow * ROWB + lch * 16;
    const size_t  s0 = (size_t)lrow * DDIM + lch * 8;

    // ldmatrix lane mappings
    const int a_r = lane & 15;
    const int a_c = lane >> 4;
    const int b_r = (lane & 7) | ((lane & 16) >> 1);
    const int b_h = (lane >> 3) & 1;
    const uint32_t sA = (wm * 64 + a_r) * ROWB + a_c * 16;
    const uint32_t sB = (wn * 16 + b_r) * ROWB + b_h * 16;

    float cP[4][2][4];
    float cA[4][2][4];
    #pragma unroll
    for (int mt = 0; mt < 4; mt++)
        #pragma unroll
        for (int nt = 0; nt < 2; nt++)
            #pragma unroll
            for (int i = 0; i < 4; i++) { cP[mt][nt][i] = 0.f; cA[mt][nt][i] = 0.f; }

    // prologue: stages 0..2
    #pragma unroll
    for (int s = 0; s < NSTG - 1; s++) {
        const uint32_t db = sb + s * STAGEB;
        const size_t ko = (size_t)s * BK;
        #pragma unroll
        for (int t = 0; t < 3; t++)
            CP_ASYNC16(db + t * TILEB + d0, srcs[t] + s0 + ko);
        asm volatile("cp.async.commit_group;" ::: "memory");
    }

    for (int k = 0; k < NKIT; k++) {
        asm volatile("cp.async.wait_group %0;" :: "n"(NSTG - 2) : "memory");
        __syncthreads();

        if (k + NSTG - 1 < NKIT) {
            const uint32_t db = sb + ((k + NSTG - 1) & (NSTG - 1)) * STAGEB;
            const size_t ko = (size_t)(k + NSTG - 1) * BK;
            #pragma unroll
            for (int t = 0; t < 3; t++)
                CP_ASYNC16(db + t * TILEB + d0, srcs[t] + s0 + ko);
        }
        asm volatile("cp.async.commit_group;" ::: "memory");

        const uint32_t st = sb + (k & (NSTG - 1)) * STAGEB;
        #pragma unroll
        for (int ks = 0; ks < 2; ks++) {
            const uint32_t kofs = ks * 32;   // 16 bf16 = 32 bytes along K
            uint32_t xh[4][4];
            #pragma unroll
            for (int mt = 0; mt < 4; mt++)
                LDSM4(xh[mt], st + 0 * TILEB + sA + mt * 16 * ROWB + kofs);

            uint32_t bp[4], ba[4];
            LDSM4(bp, st + 1 * TILEB + sB + kofs);
            LDSM4(ba, st + 2 * TILEB + sB + kofs);
            #pragma unroll
            for (int mt = 0; mt < 4; mt++) {
                #pragma unroll
                for (int nt = 0; nt < 2; nt++) {
                    MMA16816(cP[mt][nt], xh[mt], bp[nt * 2], bp[nt * 2 + 1]);
                    MMA16816(cA[mt][nt], xh[mt], ba[nt * 2], ba[nt * 2 + 1]);
                }
            }
        }
    }

    // epilogue
    const int g  = lane >> 2;
    const int tg = lane & 3;
    #pragma unroll
    for (int mt = 0; mt < 4; mt++) {
        #pragma unroll
        for (int h = 0; h < 2; h++) {
            const int row = rb + wm * 64 + mt * 16 + h * 8 + g;
            const float x2 = g_x2[row];
            float* orow = out + (size_t)row * CDIM + cb + wn * 16;
            #pragma unroll
            for (int nt = 0; nt < 2; nt++) {
                const int col = cb + wn * 16 + nt * 8 + tg * 2;
                float2 r;
                r.x = hyp_logit(cP[mt][nt][2 * h],     cA[mt][nt][2 * h],     x2,
                                g_p2[col],     g_pa[col],     g_an[col]);
                r.y = hyp_logit(cP[mt][nt][2 * h + 1], cA[mt][nt][2 * h + 1], x2,
                                g_p2[col + 1], g_pa[col + 1], g_an[col + 1]);
                *(float2*)(orow + nt * 8 + tg * 2) = r;
            }
        }
    }
}

// ---------------------------------------------------------------------------
extern "C" void kernel_launch(void* const* d_in, const int* in_sizes, int n_in,
                              void* d_out, int out_size) {
    const float* x = (const float*)d_in[0];
    const float* a = (const float*)d_in[1];
    const float* p = (const float*)d_in[2];
    float* out = (float*)d_out;

    cudaFuncSetAttribute(mlr_mma_kernel,
                         cudaFuncAttributeMaxDynamicSharedMemorySize, SMEM_NEED);

    proj_split_kernel<<<BDIM, 256>>>(x);
    stats_split_kernel<<<CDIM, 256>>>(a, p);
    dim3 grid(CDIM / BN, BDIM / BM);
    mlr_mma_kernel<<<grid, 512, SMEM_NEED>>>(out);
}